// round 6
// baseline (speedup 1.0000x reference)
#include <cuda_runtime.h>
#include <cuda_bf16.h>
#include <cstdint>
#include <math.h>

// ---------------- problem constants ----------------
#define B_ 8192
#define D_ 4096
#define H_ 8192
#define C_ 2

// ---------------- tiling ----------------
#define BM 128
#define BN 128
#define KC 32                    // bf16 K elems per stage (64 bytes per row)
#define NIT (D_ / KC)            // 128
#define NBLK_N (H_ / BN)         // 64
#define NBLK_M (B_ / BM)         // 64
#define NSTAGE 3

// stage layout (bytes): 4 parts of 128 rows x 64B
#define PART_BYTES (128 * 64)            // 8192
#define OFF_AH 0
#define OFF_AL (PART_BYTES)
#define OFF_BH (2 * PART_BYTES)
#define OFF_BL (3 * PART_BYTES)
#define STAGE_BYTES (4 * PART_BYTES)     // 32768
#define DSMEM_BYTES (NSTAGE * STAGE_BYTES)   // 98304

// ---------------- device scratch (no allocs allowed) ----------------
__device__ __nv_bfloat16 g_xhi[(size_t)B_ * D_];
__device__ __nv_bfloat16 g_xlo[(size_t)B_ * D_];
__device__ __nv_bfloat16 g_w1T_hi[2][(size_t)H_ * D_];
__device__ __nv_bfloat16 g_w1T_lo[2][(size_t)H_ * D_];
__device__ float g_part[2][NBLK_N][B_][C_];

// ---------------- helpers ----------------
__device__ __forceinline__ uint32_t smem_u32(const void* p) {
    uint32_t a;
    asm("{ .reg .u64 t; cvta.to.shared.u64 t, %1; cvt.u32.u64 %0, t; }" : "=r"(a) : "l"(p));
    return a;
}
__device__ __forceinline__ uint64_t to_global(const void* p) {
    uint64_t g; asm("cvta.to.global.u64 %0, %1;" : "=l"(g) : "l"(p)); return g;
}
__device__ __forceinline__ void cpa16(uint32_t s, uint64_t g) {
    asm volatile("cp.async.cg.shared.global [%0], [%1], 16;" :: "r"(s), "l"(g));
}
__device__ __forceinline__ void cpa_commit() { asm volatile("cp.async.commit_group;" ::: "memory"); }

__device__ __forceinline__ void ldsm4(uint32_t addr, uint32_t r[4]) {
    asm volatile("ldmatrix.sync.aligned.m8n8.x4.shared.b16 {%0,%1,%2,%3}, [%4];"
        : "=r"(r[0]), "=r"(r[1]), "=r"(r[2]), "=r"(r[3]) : "r"(addr));
}
__device__ __forceinline__ void mma16816(float c[4], const uint32_t a[4], uint32_t b0, uint32_t b1) {
    asm volatile("mma.sync.aligned.m16n8k16.row.col.f32.bf16.bf16.f32 "
        "{%0,%1,%2,%3},{%4,%5,%6,%7},{%8,%9},{%0,%1,%2,%3};"
        : "+f"(c[0]), "+f"(c[1]), "+f"(c[2]), "+f"(c[3])
        : "r"(a[0]), "r"(a[1]), "r"(a[2]), "r"(a[3]), "r"(b0), "r"(b1));
}

// swizzled byte offset for (row, 16B-chunk) inside a 128x64B part
__device__ __forceinline__ uint32_t swz(int row, int ch) {
    return (uint32_t)(row * 64 + ((ch ^ ((row >> 1) & 3)) << 4));
}

// ---------------- conversion kernels ----------------
__global__ void convert_x_kernel(const float* __restrict__ x) {
    size_t i = (size_t)blockIdx.x * blockDim.x + threadIdx.x;
    size_t n = (size_t)B_ * D_;
    size_t stride = (size_t)gridDim.x * blockDim.x;
    for (; i < n; i += stride) {
        float v = x[i];
        __nv_bfloat16 hi = __float2bfloat16_rn(v);
        __nv_bfloat16 lo = __float2bfloat16_rn(v - __bfloat162float(hi));
        g_xhi[i] = hi; g_xlo[i] = lo;
    }
}

__global__ void transpose_w1_kernel(const float* __restrict__ w, int e) {
    __shared__ float t[32][33];
    int tx = threadIdx.x, ty = threadIdx.y;
    int hb = blockIdx.x * 32;   // H origin
    int db = blockIdx.y * 32;   // D origin
    #pragma unroll
    for (int j = 0; j < 4; j++) {
        int d = db + ty + j * 8;
        t[ty + j * 8][tx] = w[(size_t)d * H_ + hb + tx];
    }
    __syncthreads();
    #pragma unroll
    for (int j = 0; j < 4; j++) {
        int h = hb + ty + j * 8;
        float v = t[tx][ty + j * 8];           // w1[db+tx][h]
        __nv_bfloat16 hi = __float2bfloat16_rn(v);
        __nv_bfloat16 lo = __float2bfloat16_rn(v - __bfloat162float(hi));
        size_t o = (size_t)h * D_ + db + tx;
        g_w1T_hi[e][o] = hi; g_w1T_lo[e][o] = lo;
    }
}

// ---------------- fused GEMM1(+bias,ReLU) x w2 ----------------
__global__ __launch_bounds__(256, 2)
void fused_mlp_mma(const float* __restrict__ t_b1, const float* __restrict__ t_w2,
                   const float* __restrict__ f_b1, const float* __restrict__ f_w2)
{
    extern __shared__ char dsm[];
    __shared__ float s_ep[2][BM][2];

    const int tid = threadIdx.x;
    const int lane = tid & 31;
    const int wid = tid >> 5;
    const int warp_m = wid & 3;        // 4 row-bands of 32
    const int warp_n = wid >> 2;       // 2 col-halves of 64

    const uint32_t dbase = smem_u32(dsm);

    // CTA swizzle: groups of 8 m-rows iterate m fastest, then n
    const int e = blockIdx.z;
    const int bid = blockIdx.y * gridDim.x + blockIdx.x;
    const int grp = bid >> 9;               // / (8*64)
    const int r = bid & 511;
    const int mrow = (grp << 3) + (r & 7);
    const int ncol = r >> 3;
    const int m0 = mrow * BM;
    const int n0 = ncol * BN;

    // ---- producer precompute: 2 granule streams per part ----
    // granule g = tid + i*256, row = g>>2, ch = g&3
    uint32_t p_so[2];
    uint64_t p_go[2];
    #pragma unroll
    for (int i = 0; i < 2; i++) {
        const int g = tid + i * 256;
        const int row = g >> 2, ch = g & 3;
        p_so[i] = swz(row, ch);
        p_go[i] = (uint64_t)row * (D_ * 2) + (uint64_t)ch * 16;
    }
    const uint64_t gAh = to_global(g_xhi) + (uint64_t)m0 * (D_ * 2);
    const uint64_t gAl = to_global(g_xlo) + (uint64_t)m0 * (D_ * 2);
    const uint64_t gBh = to_global(g_w1T_hi[e]) + (uint64_t)n0 * (D_ * 2);
    const uint64_t gBl = to_global(g_w1T_lo[e]) + (uint64_t)n0 * (D_ * 2);

    // ---- consumer precompute: swizzled ldsm offsets for both ks phases ----
    const int lr = lane & 15;          // ldmatrix row lane
    const int lc = lane >> 4;          // ldmatrix chunk lane (0/1)
    const int m_off = warp_m * 32;
    const int n_off = warp_n * 64;

    uint32_t offA[2][2];   // [ks][mb] -> AH offset (AL = +PART_BYTES)
    uint32_t offB[2][4];   // [ks][g]  -> BH offset (BL = +PART_BYTES)
    #pragma unroll
    for (int ks = 0; ks < 2; ks++) {
        const int ch = ks * 2 + lc;
        #pragma unroll
        for (int mb = 0; mb < 2; mb++)
            offA[ks][mb] = OFF_AH + swz(m_off + mb * 16 + lr, ch);
        #pragma unroll
        for (int g = 0; g < 4; g++)
            offB[ks][g] = OFF_BH + swz(n_off + g * 16 + lr, ch);
    }

    // acc[mblock][nblock][frag]
    float acc[2][8][4];
    #pragma unroll
    for (int i = 0; i < 2; i++)
        #pragma unroll
        for (int j = 0; j < 8; j++)
            #pragma unroll
            for (int k = 0; k < 4; k++) acc[i][j][k] = 0.f;

    // ---- load one stage (kb = byte offset along K) ----
    auto load_stage = [&](uint32_t sb, uint64_t kb) {
        #pragma unroll
        for (int i = 0; i < 2; i++) {
            const uint32_t so = p_so[i];
            const uint64_t go = p_go[i] + kb;
            cpa16(sb + OFF_AH + so, gAh + go);
            cpa16(sb + OFF_AL + so, gAl + go);
            cpa16(sb + OFF_BH + so, gBh + go);
            cpa16(sb + OFF_BL + so, gBl + go);
        }
        cpa_commit();
    };

    // prologue: stages 0,1
    load_stage(dbase, 0);
    load_stage(dbase + STAGE_BYTES, 64);

    uint32_t sb = dbase;                        // consume ptr
    uint32_t pb = dbase + 2 * STAGE_BYTES;      // produce ptr
    uint64_t kb = 128;                          // next load K byte offset

    for (int it = 0; it < NIT; it++) {
        asm volatile("cp.async.wait_group 1;" ::: "memory");
        __syncthreads();

        if (it + 2 < NIT) {
            load_stage(pb, kb);
            kb += 64;
            pb += STAGE_BYTES;
            if (pb == dbase + NSTAGE * STAGE_BYTES) pb = dbase;
        } else {
            cpa_commit();   // keep wait_group bookkeeping uniform
        }

        #pragma unroll
        for (int ks = 0; ks < 2; ks++) {
            uint32_t aH[2][4], aL[2][4], bH[4][4], bL[4][4];
            #pragma unroll
            for (int mb = 0; mb < 2; mb++) {
                const uint32_t a = sb + offA[ks][mb];
                ldsm4(a, aH[mb]);
                ldsm4(a + PART_BYTES, aL[mb]);
            }
            #pragma unroll
            for (int g = 0; g < 4; g++) {
                const uint32_t a = sb + offB[ks][g];
                ldsm4(a, bH[g]);
                ldsm4(a + PART_BYTES, bL[g]);
            }
            #pragma unroll
            for (int mb = 0; mb < 2; mb++)
                #pragma unroll
                for (int nb = 0; nb < 8; nb++) {
                    const int g = nb >> 1, o = nb & 1;
                    mma16816(acc[mb][nb], aH[mb], bH[g][o], bH[g][o + 2]);
                    mma16816(acc[mb][nb], aL[mb], bH[g][o], bH[g][o + 2]);
                    mma16816(acc[mb][nb], aH[mb], bL[g][o], bL[g][o + 2]);
                }
        }
        sb += STAGE_BYTES;
        if (sb == dbase + NSTAGE * STAGE_BYTES) sb = dbase;
    }
    asm volatile("cp.async.wait_group 0;" ::: "memory");

    // ---- epilogue: bias + ReLU + contract with w2 -> per-row partials ----
    const float* __restrict__ b1 = e ? f_b1 : t_b1;
    const float* __restrict__ w2 = e ? f_w2 : t_w2;

    const int qr = lane >> 2;   // acc row within 8
    const int qc = lane & 3;    // acc col pair

    float s[2][2][2];           // [mblock][rowhalf][class]
    #pragma unroll
    for (int i = 0; i < 2; i++)
        #pragma unroll
        for (int j = 0; j < 2; j++) { s[i][j][0] = 0.f; s[i][j][1] = 0.f; }

    #pragma unroll
    for (int nb = 0; nb < 8; nb++) {
        const int col = n0 + n_off + nb * 8 + qc * 2;
        const float bias0 = __ldg(&b1[col]);
        const float bias1 = __ldg(&b1[col + 1]);
        const float w200 = __ldg(&w2[col * 2 + 0]);
        const float w201 = __ldg(&w2[col * 2 + 1]);
        const float w210 = __ldg(&w2[col * 2 + 2]);
        const float w211 = __ldg(&w2[col * 2 + 3]);
        #pragma unroll
        for (int mb = 0; mb < 2; mb++) {
            float h;
            h = fmaxf(acc[mb][nb][0] + bias0, 0.f); s[mb][0][0] += h * w200; s[mb][0][1] += h * w201;
            h = fmaxf(acc[mb][nb][1] + bias1, 0.f); s[mb][0][0] += h * w210; s[mb][0][1] += h * w211;
            h = fmaxf(acc[mb][nb][2] + bias0, 0.f); s[mb][1][0] += h * w200; s[mb][1][1] += h * w201;
            h = fmaxf(acc[mb][nb][3] + bias1, 0.f); s[mb][1][0] += h * w210; s[mb][1][1] += h * w211;
        }
    }

    // quad butterfly reduce (fixed order -> deterministic)
    #pragma unroll
    for (int mb = 0; mb < 2; mb++)
        #pragma unroll
        for (int rh = 0; rh < 2; rh++)
            #pragma unroll
            for (int c = 0; c < 2; c++) {
                float v = s[mb][rh][c];
                v += __shfl_xor_sync(0xffffffffu, v, 1);
                v += __shfl_xor_sync(0xffffffffu, v, 2);
                s[mb][rh][c] = v;
            }

    if (qc == 0) {
        #pragma unroll
        for (int mb = 0; mb < 2; mb++)
            #pragma unroll
            for (int rh = 0; rh < 2; rh++) {
                const int row = warp_m * 32 + mb * 16 + rh * 8 + qr;
                s_ep[warp_n][row][0] = s[mb][rh][0];
                s_ep[warp_n][row][1] = s[mb][rh][1];
            }
    }
    __syncthreads();

    {
        const int row = tid >> 1, c = tid & 1;
        g_part[e][ncol][m0 + row][c] = s_ep[0][row][c] + s_ep[1][row][c];
    }
}

// ---------------- finalize ----------------
__global__ void finalize_kernel(const float* __restrict__ t_b2,
                                const float* __restrict__ f_b2,
                                float* __restrict__ out)
{
    const int row = blockIdx.x * blockDim.x + threadIdx.x;
    if (row >= B_) return;
    float t0 = t_b2[0], t1 = t_b2[1];
    float f0 = f_b2[0], f1 = f_b2[1];
    #pragma unroll 4
    for (int kb = 0; kb < NBLK_N; kb++) {
        t0 += g_part[0][kb][row][0];
        t1 += g_part[0][kb][row][1];
        f0 += g_part[1][kb][row][0];
        f1 += g_part[1][kb][row][1];
    }
    const float m  = fmaxf(t0, t1);
    const float e0 = __expf(t0 - m);
    const float e1 = __expf(t1 - m);
    const float conf = fmaxf(e0, e1) / (e0 + e1);
    const bool low = conf < 0.8f;
    out[row * 2 + 0] = low ? f0 : t0;
    out[row * 2 + 1] = low ? f1 : t1;
}

// ---------------- launch ----------------
extern "C" void kernel_launch(void* const* d_in, const int* in_sizes, int n_in,
                              void* d_out, int out_size)
{
    const float* x    = (const float*)d_in[0];
    const float* t_w1 = (const float*)d_in[1];
    const float* t_b1 = (const float*)d_in[2];
    const float* t_w2 = (const float*)d_in[3];
    const float* t_b2 = (const float*)d_in[4];
    const float* f_w1 = (const float*)d_in[5];
    const float* f_b1 = (const float*)d_in[6];
    const float* f_w2 = (const float*)d_in[7];
    const float* f_b2 = (const float*)d_in[8];
    float* out = (float*)d_out;

    cudaFuncSetAttribute(fused_mlp_mma, cudaFuncAttributeMaxDynamicSharedMemorySize, DSMEM_BYTES);

    convert_x_kernel<<<1024, 256>>>(x);
    dim3 tg(H_ / 32, D_ / 32);
    transpose_w1_kernel<<<tg, dim3(32, 8)>>>(t_w1, 0);
    transpose_w1_kernel<<<tg, dim3(32, 8)>>>(f_w1, 1);

    dim3 grid(NBLK_N, NBLK_M, 2);   // 64 x 64 x 2, remapped in-kernel
    fused_mlp_mma<<<grid, 256, DSMEM_BYTES>>>(t_b1, t_w2, f_b1, f_w2);

    finalize_kernel<<<(B_ + 255) / 256, 256>>>(t_b2, f_b2, out);
}

// round 7
// speedup vs baseline: 1.0268x; 1.0268x over previous
#include <cuda_runtime.h>
#include <cuda_bf16.h>
#include <cstdint>
#include <math.h>

// ---------------- problem constants ----------------
#define B_ 8192
#define D_ 4096
#define H_ 8192
#define C_ 2

// ---------------- tiling ----------------
#define BM 128
#define BN 128
#define KC 32                    // bf16 K elems per stage (64 bytes per row)
#define NIT (D_ / KC)            // 128
#define NBLK_N (H_ / BN)         // 64
#define NBLK_M (B_ / BM)         // 64
#define NSTAGE 3

// stage layout (bytes): 4 parts of 128 rows x 64B
#define PART_BYTES (128 * 64)            // 8192
#define OFF_AH 0
#define OFF_AL (PART_BYTES)
#define OFF_BH (2 * PART_BYTES)
#define OFF_BL (3 * PART_BYTES)
#define STAGE_BYTES (4 * PART_BYTES)     // 32768
#define DSMEM_BYTES (NSTAGE * STAGE_BYTES)   // 98304

// ---------------- device scratch (no allocs allowed) ----------------
__device__ __nv_bfloat16 g_xhi[(size_t)B_ * D_];
__device__ __nv_bfloat16 g_xlo[(size_t)B_ * D_];
__device__ __nv_bfloat16 g_w1T_hi[2][(size_t)H_ * D_];
__device__ __nv_bfloat16 g_w1T_lo[2][(size_t)H_ * D_];
__device__ float g_part[2][NBLK_N][B_][C_];

// ---------------- helpers ----------------
__device__ __forceinline__ uint32_t smem_u32(const void* p) {
    uint32_t a;
    asm("{ .reg .u64 t; cvta.to.shared.u64 t, %1; cvt.u32.u64 %0, t; }" : "=r"(a) : "l"(p));
    return a;
}
__device__ __forceinline__ uint64_t to_global(const void* p) {
    uint64_t g; asm("cvta.to.global.u64 %0, %1;" : "=l"(g) : "l"(p)); return g;
}
__device__ __forceinline__ void cpa16(uint32_t s, uint64_t g) {
    asm volatile("cp.async.cg.shared.global [%0], [%1], 16;" :: "r"(s), "l"(g));
}
__device__ __forceinline__ void cpa_commit() { asm volatile("cp.async.commit_group;" ::: "memory"); }

__device__ __forceinline__ void ldsm4(uint32_t addr, uint32_t r[4]) {
    asm volatile("ldmatrix.sync.aligned.m8n8.x4.shared.b16 {%0,%1,%2,%3}, [%4];"
        : "=r"(r[0]), "=r"(r[1]), "=r"(r[2]), "=r"(r[3]) : "r"(addr));
}
__device__ __forceinline__ void mma16816(float c[4], const uint32_t a[4], uint32_t b0, uint32_t b1) {
    asm volatile("mma.sync.aligned.m16n8k16.row.col.f32.bf16.bf16.f32 "
        "{%0,%1,%2,%3},{%4,%5,%6,%7},{%8,%9},{%0,%1,%2,%3};"
        : "+f"(c[0]), "+f"(c[1]), "+f"(c[2]), "+f"(c[3])
        : "r"(a[0]), "r"(a[1]), "r"(a[2]), "r"(a[3]), "r"(b0), "r"(b1));
}

// swizzled byte offset for (row, 16B-chunk) inside a 128x64B part
__device__ __forceinline__ uint32_t swz(int row, int ch) {
    return (uint32_t)(row * 64 + ((ch ^ ((row >> 1) & 3)) << 4));
}

// ---------------- conversion kernels ----------------
__global__ void convert_x_kernel(const float* __restrict__ x) {
    size_t i = (size_t)blockIdx.x * blockDim.x + threadIdx.x;
    size_t n = (size_t)B_ * D_;
    size_t stride = (size_t)gridDim.x * blockDim.x;
    for (; i < n; i += stride) {
        float v = x[i];
        __nv_bfloat16 hi = __float2bfloat16_rn(v);
        __nv_bfloat16 lo = __float2bfloat16_rn(v - __bfloat162float(hi));
        g_xhi[i] = hi; g_xlo[i] = lo;
    }
}

__global__ void transpose_w1_kernel(const float* __restrict__ w, int e) {
    __shared__ float t[32][33];
    int tx = threadIdx.x, ty = threadIdx.y;
    int hb = blockIdx.x * 32;   // H origin
    int db = blockIdx.y * 32;   // D origin
    #pragma unroll
    for (int j = 0; j < 4; j++) {
        int d = db + ty + j * 8;
        t[ty + j * 8][tx] = w[(size_t)d * H_ + hb + tx];
    }
    __syncthreads();
    #pragma unroll
    for (int j = 0; j < 4; j++) {
        int h = hb + ty + j * 8;
        float v = t[tx][ty + j * 8];           // w1[db+tx][h]
        __nv_bfloat16 hi = __float2bfloat16_rn(v);
        __nv_bfloat16 lo = __float2bfloat16_rn(v - __bfloat162float(hi));
        size_t o = (size_t)h * D_ + db + tx;
        g_w1T_hi[e][o] = hi; g_w1T_lo[e][o] = lo;
    }
}

// ---------------- fused GEMM1(+bias,ReLU) x w2 ----------------
__global__ __launch_bounds__(256, 2)
void fused_mlp_mma(const float* __restrict__ t_b1, const float* __restrict__ t_w2,
                   const float* __restrict__ f_b1, const float* __restrict__ f_w2)
{
    extern __shared__ char dsm[];
    __shared__ float s_ep[2][BM][2];

    const int tid = threadIdx.x;
    const int lane = tid & 31;
    const int wid = tid >> 5;
    const int warp_m = wid & 3;        // 4 row-bands of 32
    const int warp_n = wid >> 2;       // 2 col-halves of 64

    const uint32_t dbase = smem_u32(dsm);

    // CTA swizzle: groups of 8 m-rows iterate m fastest, then n
    const int e = blockIdx.z;
    const int bid = blockIdx.y * gridDim.x + blockIdx.x;
    const int grp = bid >> 9;               // / (8*64)
    const int r = bid & 511;
    const int mrow = (grp << 3) + (r & 7);
    const int ncol = r >> 3;
    const int m0 = mrow * BM;
    const int n0 = ncol * BN;

    // ---- producer precompute: 2 granule streams per part ----
    uint32_t p_so[2];
    uint64_t p_go[2];
    #pragma unroll
    for (int i = 0; i < 2; i++) {
        const int g = tid + i * 256;
        const int row = g >> 2, ch = g & 3;
        p_so[i] = swz(row, ch);
        p_go[i] = (uint64_t)row * (D_ * 2) + (uint64_t)ch * 16;
    }
    const uint64_t gAh = to_global(g_xhi) + (uint64_t)m0 * (D_ * 2);
    const uint64_t gAl = to_global(g_xlo) + (uint64_t)m0 * (D_ * 2);
    const uint64_t gBh = to_global(g_w1T_hi[e]) + (uint64_t)n0 * (D_ * 2);
    const uint64_t gBl = to_global(g_w1T_lo[e]) + (uint64_t)n0 * (D_ * 2);

    // ---- consumer precompute: 4 absolute base addresses; all other LDSM
    // addresses are base + compile-time immediates.
    // Invariance used: swz(row+16, ch) == swz(row, ch) + 1024 (verified:
    // (row+16)>>1 adds 8, which is 0 mod 4, so the XOR term is unchanged).
    const int lr = lane & 15;          // ldmatrix row lane
    const int lc = lane >> 4;          // ldmatrix chunk lane (0/1)
    const int m_off = warp_m * 32;
    const int n_off = warp_n * 64;

    uint32_t baseA[2], baseB[2];       // [ks]
    #pragma unroll
    for (int ks = 0; ks < 2; ks++) {
        const int ch = ks * 2 + lc;
        baseA[ks] = dbase + OFF_AH + swz(m_off + lr, ch);
        baseB[ks] = dbase + OFF_BH + swz(n_off + lr, ch);
    }

    // acc[mblock][nblock][frag]
    float acc[2][8][4];
    #pragma unroll
    for (int i = 0; i < 2; i++)
        #pragma unroll
        for (int j = 0; j < 8; j++)
            #pragma unroll
            for (int k = 0; k < 4; k++) acc[i][j][k] = 0.f;

    // ---- load one stage (kb = byte offset along K) ----
    auto load_stage = [&](uint32_t sb, uint64_t kb) {
        #pragma unroll
        for (int i = 0; i < 2; i++) {
            const uint32_t so = p_so[i];
            const uint64_t go = p_go[i] + kb;
            cpa16(sb + OFF_AH + so, gAh + go);
            cpa16(sb + OFF_AL + so, gAl + go);
            cpa16(sb + OFF_BH + so, gBh + go);
            cpa16(sb + OFF_BL + so, gBl + go);
        }
        cpa_commit();
    };

    // prologue: stages 0,1
    load_stage(dbase, 0);
    load_stage(dbase + STAGE_BYTES, 64);

    uint32_t pb = dbase + 2 * STAGE_BYTES;      // produce ptr
    uint64_t kb = 128;                          // next load K byte offset
    int stg = 0;                                // consume stage index

    for (int it = 0; it < NIT; it++) {
        asm volatile("cp.async.wait_group 1;" ::: "memory");
        __syncthreads();

        if (it + 2 < NIT) {
            load_stage(pb, kb);
            kb += 64;
            pb += STAGE_BYTES;
            if (pb == dbase + NSTAGE * STAGE_BYTES) pb = dbase;
        } else {
            cpa_commit();   // keep wait_group bookkeeping uniform
        }

        #pragma unroll
        for (int ks = 0; ks < 2; ks++) {
            uint32_t aH[2][4], aL[2][4];
            ldsm4(baseA[ks],                      aH[0]);
            ldsm4(baseA[ks] + 1024,               aH[1]);
            ldsm4(baseA[ks] + PART_BYTES,         aL[0]);
            ldsm4(baseA[ks] + PART_BYTES + 1024,  aL[1]);
            #pragma unroll
            for (int g = 0; g < 4; g++) {
                uint32_t bH[4], bL[4];
                ldsm4(baseB[ks] + g * 1024,              bH);
                ldsm4(baseB[ks] + g * 1024 + PART_BYTES, bL);
                #pragma unroll
                for (int mb = 0; mb < 2; mb++)
                    #pragma unroll
                    for (int o = 0; o < 2; o++) {
                        float* a = acc[mb][g * 2 + o];
                        mma16816(a, aH[mb], bH[o], bH[o + 2]);
                        mma16816(a, aL[mb], bH[o], bH[o + 2]);
                        mma16816(a, aH[mb], bL[o], bL[o + 2]);
                    }
            }
        }

        // advance consume bases (wrap every NSTAGE iterations)
        if (++stg == NSTAGE) {
            stg = 0;
            baseA[0] -= (NSTAGE - 1) * STAGE_BYTES;
            baseA[1] -= (NSTAGE - 1) * STAGE_BYTES;
            baseB[0] -= (NSTAGE - 1) * STAGE_BYTES;
            baseB[1] -= (NSTAGE - 1) * STAGE_BYTES;
        } else {
            baseA[0] += STAGE_BYTES;
            baseA[1] += STAGE_BYTES;
            baseB[0] += STAGE_BYTES;
            baseB[1] += STAGE_BYTES;
        }
    }
    asm volatile("cp.async.wait_group 0;" ::: "memory");

    // ---- epilogue: bias + ReLU + contract with w2 -> per-row partials ----
    const float* __restrict__ b1 = e ? f_b1 : t_b1;
    const float* __restrict__ w2 = e ? f_w2 : t_w2;

    const int qr = lane >> 2;   // acc row within 8
    const int qc = lane & 3;    // acc col pair

    float s[2][2][2];           // [mblock][rowhalf][class]
    #pragma unroll
    for (int i = 0; i < 2; i++)
        #pragma unroll
        for (int j = 0; j < 2; j++) { s[i][j][0] = 0.f; s[i][j][1] = 0.f; }

    #pragma unroll
    for (int nb = 0; nb < 8; nb++) {
        const int col = n0 + n_off + nb * 8 + qc * 2;
        const float bias0 = __ldg(&b1[col]);
        const float bias1 = __ldg(&b1[col + 1]);
        const float w200 = __ldg(&w2[col * 2 + 0]);
        const float w201 = __ldg(&w2[col * 2 + 1]);
        const float w210 = __ldg(&w2[col * 2 + 2]);
        const float w211 = __ldg(&w2[col * 2 + 3]);
        #pragma unroll
        for (int mb = 0; mb < 2; mb++) {
            float h;
            h = fmaxf(acc[mb][nb][0] + bias0, 0.f); s[mb][0][0] += h * w200; s[mb][0][1] += h * w201;
            h = fmaxf(acc[mb][nb][1] + bias1, 0.f); s[mb][0][0] += h * w210; s[mb][0][1] += h * w211;
            h = fmaxf(acc[mb][nb][2] + bias0, 0.f); s[mb][1][0] += h * w200; s[mb][1][1] += h * w201;
            h = fmaxf(acc[mb][nb][3] + bias1, 0.f); s[mb][1][0] += h * w210; s[mb][1][1] += h * w211;
        }
    }

    // quad butterfly reduce (fixed order -> deterministic)
    #pragma unroll
    for (int mb = 0; mb < 2; mb++)
        #pragma unroll
        for (int rh = 0; rh < 2; rh++)
            #pragma unroll
            for (int c = 0; c < 2; c++) {
                float v = s[mb][rh][c];
                v += __shfl_xor_sync(0xffffffffu, v, 1);
                v += __shfl_xor_sync(0xffffffffu, v, 2);
                s[mb][rh][c] = v;
            }

    if (qc == 0) {
        #pragma unroll
        for (int mb = 0; mb < 2; mb++)
            #pragma unroll
            for (int rh = 0; rh < 2; rh++) {
                const int row = warp_m * 32 + mb * 16 + rh * 8 + qr;
                s_ep[warp_n][row][0] = s[mb][rh][0];
                s_ep[warp_n][row][1] = s[mb][rh][1];
            }
    }
    __syncthreads();

    {
        const int row = tid >> 1, c = tid & 1;
        g_part[e][ncol][m0 + row][c] = s_ep[0][row][c] + s_ep[1][row][c];
    }
}

// ---------------- finalize ----------------
__global__ void finalize_kernel(const float* __restrict__ t_b2,
                                const float* __restrict__ f_b2,
                                float* __restrict__ out)
{
    const int row = blockIdx.x * blockDim.x + threadIdx.x;
    if (row >= B_) return;
    float t0 = t_b2[0], t1 = t_b2[1];
    float f0 = f_b2[0], f1 = f_b2[1];
    #pragma unroll 4
    for (int kb = 0; kb < NBLK_N; kb++) {
        t0 += g_part[0][kb][row][0];
        t1 += g_part[0][kb][row][1];
        f0 += g_part[1][kb][row][0];
        f1 += g_part[1][kb][row][1];
    }
    const float m  = fmaxf(t0, t1);
    const float e0 = __expf(t0 - m);
    const float e1 = __expf(t1 - m);
    const float conf = fmaxf(e0, e1) / (e0 + e1);
    const bool low = conf < 0.8f;
    out[row * 2 + 0] = low ? f0 : t0;
    out[row * 2 + 1] = low ? f1 : t1;
}

// ---------------- launch ----------------
extern "C" void kernel_launch(void* const* d_in, const int* in_sizes, int n_in,
                              void* d_out, int out_size)
{
    const float* x    = (const float*)d_in[0];
    const float* t_w1 = (const float*)d_in[1];
    const float* t_b1 = (const float*)d_in[2];
    const float* t_w2 = (const float*)d_in[3];
    const float* t_b2 = (const float*)d_in[4];
    const float* f_w1 = (const float*)d_in[5];
    const float* f_b1 = (const float*)d_in[6];
    const float* f_w2 = (const float*)d_in[7];
    const float* f_b2 = (const float*)d_in[8];
    float* out = (float*)d_out;

    cudaFuncSetAttribute(fused_mlp_mma, cudaFuncAttributeMaxDynamicSharedMemorySize, DSMEM_BYTES);
    cudaFuncSetAttribute(fused_mlp_mma, cudaFuncAttributePreferredSharedMemoryCarveout, 100);

    convert_x_kernel<<<1024, 256>>>(x);
    dim3 tg(H_ / 32, D_ / 32);
    transpose_w1_kernel<<<tg, dim3(32, 8)>>>(t_w1, 0);
    transpose_w1_kernel<<<tg, dim3(32, 8)>>>(f_w1, 1);

    dim3 grid(NBLK_N, NBLK_M, 2);   // 64 x 64 x 2, remapped in-kernel
    fused_mlp_mma<<<grid, 256, DSMEM_BYTES>>>(t_b1, t_w2, f_b1, f_w2);

    finalize_kernel<<<(B_ + 255) / 256, 256>>>(t_b2, f_b2, out);
}

// round 8
// speedup vs baseline: 1.0777x; 1.0495x over previous
#include <cuda_runtime.h>
#include <cuda_bf16.h>
#include <cstdint>
#include <math.h>

// ---------------- problem constants ----------------
#define B_ 8192
#define D_ 4096
#define H_ 8192
#define C_ 2

// ---------------- tiling ----------------
#define BM 128
#define BN 128
#define KC 32                    // bf16 K elems per stage (64 bytes per row)
#define NIT (D_ / KC)            // 128
#define NBLK_N (H_ / BN)         // 64
#define NBLK_M (B_ / BM)         // 64
#define NSTAGE 3

// stage layout (bytes): 4 parts of 128 rows x 64B
#define PART_BYTES (128 * 64)            // 8192
#define OFF_AH 0
#define OFF_AL (PART_BYTES)
#define OFF_BH (2 * PART_BYTES)
#define OFF_BL (3 * PART_BYTES)
#define STAGE_BYTES (4 * PART_BYTES)     // 32768
#define DSMEM_BYTES (NSTAGE * STAGE_BYTES)   // 98304

// granule-1 deltas (granule g=tid+256 -> row+64, same chunk):
//   gmem: +64 rows * D_*2 bytes ; smem: swz(row+64,ch)=swz(row,ch)+64*64
#define GRAN1_GOFF ((uint64_t)64 * D_ * 2)
#define GRAN1_SOFF 4096

// ---------------- device scratch (no allocs allowed) ----------------
__device__ __nv_bfloat16 g_xhi[(size_t)B_ * D_];
__device__ __nv_bfloat16 g_xlo[(size_t)B_ * D_];
__device__ __nv_bfloat16 g_w1T_hi[2][(size_t)H_ * D_];
__device__ __nv_bfloat16 g_w1T_lo[2][(size_t)H_ * D_];
__device__ float g_part[2][NBLK_N][B_][C_];

// ---------------- helpers ----------------
__device__ __forceinline__ uint32_t smem_u32(const void* p) {
    uint32_t a;
    asm("{ .reg .u64 t; cvta.to.shared.u64 t, %1; cvt.u32.u64 %0, t; }" : "=r"(a) : "l"(p));
    return a;
}
__device__ __forceinline__ uint64_t to_global(const void* p) {
    uint64_t g; asm("cvta.to.global.u64 %0, %1;" : "=l"(g) : "l"(p)); return g;
}
__device__ __forceinline__ void cpa16(uint32_t s, uint64_t g) {
    asm volatile("cp.async.cg.shared.global [%0], [%1], 16;" :: "r"(s), "l"(g));
}
__device__ __forceinline__ void cpa_commit() { asm volatile("cp.async.commit_group;" ::: "memory"); }

__device__ __forceinline__ void ldsm4(uint32_t addr, uint32_t r[4]) {
    asm volatile("ldmatrix.sync.aligned.m8n8.x4.shared.b16 {%0,%1,%2,%3}, [%4];"
        : "=r"(r[0]), "=r"(r[1]), "=r"(r[2]), "=r"(r[3]) : "r"(addr));
}
__device__ __forceinline__ void mma16816(float c[4], const uint32_t a[4], uint32_t b0, uint32_t b1) {
    asm volatile("mma.sync.aligned.m16n8k16.row.col.f32.bf16.bf16.f32 "
        "{%0,%1,%2,%3},{%4,%5,%6,%7},{%8,%9},{%0,%1,%2,%3};"
        : "+f"(c[0]), "+f"(c[1]), "+f"(c[2]), "+f"(c[3])
        : "r"(a[0]), "r"(a[1]), "r"(a[2]), "r"(a[3]), "r"(b0), "r"(b1));
}

// swizzled byte offset for (row, 16B-chunk) inside a 128x64B part
__device__ __forceinline__ uint32_t swz(int row, int ch) {
    return (uint32_t)(row * 64 + ((ch ^ ((row >> 1) & 3)) << 4));
}

// ---------------- conversion kernels ----------------
__global__ void convert_x_kernel(const float* __restrict__ x) {
    size_t i = (size_t)blockIdx.x * blockDim.x + threadIdx.x;
    size_t n = (size_t)B_ * D_;
    size_t stride = (size_t)gridDim.x * blockDim.x;
    for (; i < n; i += stride) {
        float v = x[i];
        __nv_bfloat16 hi = __float2bfloat16_rn(v);
        __nv_bfloat16 lo = __float2bfloat16_rn(v - __bfloat162float(hi));
        g_xhi[i] = hi; g_xlo[i] = lo;
    }
}

__global__ void transpose_w1_kernel(const float* __restrict__ w, int e) {
    __shared__ float t[32][33];
    int tx = threadIdx.x, ty = threadIdx.y;
    int hb = blockIdx.x * 32;   // H origin
    int db = blockIdx.y * 32;   // D origin
    #pragma unroll
    for (int j = 0; j < 4; j++) {
        int d = db + ty + j * 8;
        t[ty + j * 8][tx] = w[(size_t)d * H_ + hb + tx];
    }
    __syncthreads();
    #pragma unroll
    for (int j = 0; j < 4; j++) {
        int h = hb + ty + j * 8;
        float v = t[tx][ty + j * 8];           // w1[db+tx][h]
        __nv_bfloat16 hi = __float2bfloat16_rn(v);
        __nv_bfloat16 lo = __float2bfloat16_rn(v - __bfloat162float(hi));
        size_t o = (size_t)h * D_ + db + tx;
        g_w1T_hi[e][o] = hi; g_w1T_lo[e][o] = lo;
    }
}

// ---------------- fused GEMM1(+bias,ReLU) x w2 ----------------
__global__ __launch_bounds__(256, 2)
void fused_mlp_mma(const float* __restrict__ t_b1, const float* __restrict__ t_w2,
                   const float* __restrict__ f_b1, const float* __restrict__ f_w2)
{
    extern __shared__ char dsm[];
    __shared__ float s_ep[2][BM][2];

    const int tid = threadIdx.x;
    const int lane = tid & 31;
    const int wid = tid >> 5;
    const int warp_m = wid & 3;        // 4 row-bands of 32
    const int warp_n = wid >> 2;       // 2 col-halves of 64

    const uint32_t dbase = smem_u32(dsm);

    // CTA swizzle: groups of 8 m-rows iterate m fastest, then n
    const int e = blockIdx.z;
    const int bid = blockIdx.y * gridDim.x + blockIdx.x;
    const int grp = bid >> 9;               // / (8*64)
    const int r = bid & 511;
    const int mrow = (grp << 3) + (r & 7);
    const int ncol = r >> 3;
    const int m0 = mrow * BM;
    const int n0 = ncol * BN;

    // ---- producer: granule-0 mapping; granule-1 = +GRAN1_GOFF / +GRAN1_SOFF
    const int row0 = tid >> 2, ch0 = tid & 3;
    const uint32_t sA = dbase + swz(row0, ch0);    // smem dst base (stage/part by imm)
    const uint64_t go0 = (uint64_t)row0 * (D_ * 2) + (uint64_t)ch0 * 16;

    uint64_t pAh = to_global(g_xhi)       + (uint64_t)m0 * (D_ * 2) + go0;
    uint64_t pAl = to_global(g_xlo)       + (uint64_t)m0 * (D_ * 2) + go0;
    uint64_t pBh = to_global(g_w1T_hi[e]) + (uint64_t)n0 * (D_ * 2) + go0;
    uint64_t pBl = to_global(g_w1T_lo[e]) + (uint64_t)n0 * (D_ * 2) + go0;

    // ---- consumer: 4 rotating base addresses (stage 0), rest by immediates
    const int lr = lane & 15;
    const int lc = lane >> 4;
    uint32_t baseA0 = dbase + OFF_AH + swz(warp_m * 32 + lr, lc);
    uint32_t baseA1 = dbase + OFF_AH + swz(warp_m * 32 + lr, 2 + lc);
    uint32_t baseB0 = dbase + OFF_BH + swz(warp_n * 64 + lr, lc);
    uint32_t baseB1 = dbase + OFF_BH + swz(warp_n * 64 + lr, 2 + lc);

    float acc[2][8][4];
    #pragma unroll
    for (int i = 0; i < 2; i++)
        #pragma unroll
        for (int j = 0; j < 8; j++)
            #pragma unroll
            for (int k = 0; k < 4; k++) acc[i][j][k] = 0.f;

    // ---- one stage of producer loads (stage chosen by compile-time stoff)
    auto load_stage = [&](uint32_t stoff) {
        cpa16(sA + stoff + OFF_AH,              pAh);
        cpa16(sA + stoff + OFF_AH + GRAN1_SOFF, pAh + GRAN1_GOFF);
        cpa16(sA + stoff + OFF_AL,              pAl);
        cpa16(sA + stoff + OFF_AL + GRAN1_SOFF, pAl + GRAN1_GOFF);
        cpa16(sA + stoff + OFF_BH,              pBh);
        cpa16(sA + stoff + OFF_BH + GRAN1_SOFF, pBh + GRAN1_GOFF);
        cpa16(sA + stoff + OFF_BL,              pBl);
        cpa16(sA + stoff + OFF_BL + GRAN1_SOFF, pBl + GRAN1_GOFF);
        cpa_commit();
        pAh += 64; pAl += 64; pBh += 64; pBl += 64;
    };

    // ---- consume one K chunk (2 ks phases) from current bases
    auto compute = [&]() {
        #pragma unroll
        for (int ks = 0; ks < 2; ks++) {
            const uint32_t bA = ks ? baseA1 : baseA0;
            const uint32_t bB = ks ? baseB1 : baseB0;
            uint32_t aH[2][4], aL[2][4];
            ldsm4(bA,                     aH[0]);
            ldsm4(bA + 1024,              aH[1]);
            ldsm4(bA + PART_BYTES,        aL[0]);
            ldsm4(bA + PART_BYTES + 1024, aL[1]);
            #pragma unroll
            for (int g = 0; g < 4; g++) {
                uint32_t bH[4], bL[4];
                ldsm4(bB + g * 1024,              bH);
                ldsm4(bB + g * 1024 + PART_BYTES, bL);
                #pragma unroll
                for (int mb = 0; mb < 2; mb++)
                    #pragma unroll
                    for (int o = 0; o < 2; o++) {
                        float* a = acc[mb][g * 2 + o];
                        mma16816(a, aH[mb], bH[o], bH[o + 2]);
                        mma16816(a, aL[mb], bH[o], bH[o + 2]);
                        mma16816(a, aH[mb], bL[o], bL[o + 2]);
                    }
            }
        }
    };

    // prologue: stages 0,1
    load_stage(0);
    load_stage(STAGE_BYTES);

    // main loop: 126 iterations = 42 groups of 3; stage rotation is
    // compile-time (+S, +S, -2S), producer target stage compile-time too.
    #define ITER_(PSTOFF, DELTA) do { \
        asm volatile("cp.async.wait_group 1;" ::: "memory"); \
        __syncthreads(); \
        load_stage(PSTOFF); \
        compute(); \
        baseA0 += (DELTA); baseA1 += (DELTA); \
        baseB0 += (DELTA); baseB1 += (DELTA); \
    } while (0)

    for (int o = 0; o < (NIT - 2) / 3; o++) {
        ITER_(2 * STAGE_BYTES,  STAGE_BYTES);       // it%3==0: consume s0, fill s2
        ITER_(0,                STAGE_BYTES);       // it%3==1: consume s1, fill s0
        ITER_(STAGE_BYTES,     -2 * STAGE_BYTES);   // it%3==2: consume s2, fill s1
    }
    #undef ITER_

    // epilogue iterations 126, 127 (no more loads)
    asm volatile("cp.async.wait_group 1;" ::: "memory");
    __syncthreads();
    compute();
    baseA0 += STAGE_BYTES; baseA1 += STAGE_BYTES;
    baseB0 += STAGE_BYTES; baseB1 += STAGE_BYTES;

    asm volatile("cp.async.wait_group 0;" ::: "memory");
    __syncthreads();
    compute();

    // ---- epilogue: bias + ReLU + contract with w2 -> per-row partials ----
    const float* __restrict__ b1 = e ? f_b1 : t_b1;
    const float* __restrict__ w2 = e ? f_w2 : t_w2;

    const int qr = lane >> 2;   // acc row within 8
    const int qc = lane & 3;    // acc col pair
    const int n_off = warp_n * 64;

    float s[2][2][2];           // [mblock][rowhalf][class]
    #pragma unroll
    for (int i = 0; i < 2; i++)
        #pragma unroll
        for (int j = 0; j < 2; j++) { s[i][j][0] = 0.f; s[i][j][1] = 0.f; }

    #pragma unroll
    for (int nb = 0; nb < 8; nb++) {
        const int col = n0 + n_off + nb * 8 + qc * 2;
        const float bias0 = __ldg(&b1[col]);
        const float bias1 = __ldg(&b1[col + 1]);
        const float w200 = __ldg(&w2[col * 2 + 0]);
        const float w201 = __ldg(&w2[col * 2 + 1]);
        const float w210 = __ldg(&w2[col * 2 + 2]);
        const float w211 = __ldg(&w2[col * 2 + 3]);
        #pragma unroll
        for (int mb = 0; mb < 2; mb++) {
            float h;
            h = fmaxf(acc[mb][nb][0] + bias0, 0.f); s[mb][0][0] += h * w200; s[mb][0][1] += h * w201;
            h = fmaxf(acc[mb][nb][1] + bias1, 0.f); s[mb][0][0] += h * w210; s[mb][0][1] += h * w211;
            h = fmaxf(acc[mb][nb][2] + bias0, 0.f); s[mb][1][0] += h * w200; s[mb][1][1] += h * w201;
            h = fmaxf(acc[mb][nb][3] + bias1, 0.f); s[mb][1][0] += h * w210; s[mb][1][1] += h * w211;
        }
    }

    // quad butterfly reduce (fixed order -> deterministic)
    #pragma unroll
    for (int mb = 0; mb < 2; mb++)
        #pragma unroll
        for (int rh = 0; rh < 2; rh++)
            #pragma unroll
            for (int c = 0; c < 2; c++) {
                float v = s[mb][rh][c];
                v += __shfl_xor_sync(0xffffffffu, v, 1);
                v += __shfl_xor_sync(0xffffffffu, v, 2);
                s[mb][rh][c] = v;
            }

    if (qc == 0) {
        #pragma unroll
        for (int mb = 0; mb < 2; mb++)
            #pragma unroll
            for (int rh = 0; rh < 2; rh++) {
                const int row = warp_m * 32 + mb * 16 + rh * 8 + qr;
                s_ep[warp_n][row][0] = s[mb][rh][0];
                s_ep[warp_n][row][1] = s[mb][rh][1];
            }
    }
    __syncthreads();

    {
        const int row = tid >> 1, c = tid & 1;
        g_part[e][ncol][m0 + row][c] = s_ep[0][row][c] + s_ep[1][row][c];
    }
}

// ---------------- finalize ----------------
__global__ void finalize_kernel(const float* __restrict__ t_b2,
                                const float* __restrict__ f_b2,
                                float* __restrict__ out)
{
    const int row = blockIdx.x * blockDim.x + threadIdx.x;
    if (row >= B_) return;
    float t0 = t_b2[0], t1 = t_b2[1];
    float f0 = f_b2[0], f1 = f_b2[1];
    #pragma unroll 4
    for (int kb = 0; kb < NBLK_N; kb++) {
        t0 += g_part[0][kb][row][0];
        t1 += g_part[0][kb][row][1];
        f0 += g_part[1][kb][row][0];
        f1 += g_part[1][kb][row][1];
    }
    const float m  = fmaxf(t0, t1);
    const float e0 = __expf(t0 - m);
    const float e1 = __expf(t1 - m);
    const float conf = fmaxf(e0, e1) / (e0 + e1);
    const bool low = conf < 0.8f;
    out[row * 2 + 0] = low ? f0 : t0;
    out[row * 2 + 1] = low ? f1 : t1;
}

// ---------------- launch ----------------
extern "C" void kernel_launch(void* const* d_in, const int* in_sizes, int n_in,
                              void* d_out, int out_size)
{
    const float* x    = (const float*)d_in[0];
    const float* t_w1 = (const float*)d_in[1];
    const float* t_b1 = (const float*)d_in[2];
    const float* t_w2 = (const float*)d_in[3];
    const float* t_b2 = (const float*)d_in[4];
    const float* f_w1 = (const float*)d_in[5];
    const float* f_b1 = (const float*)d_in[6];
    const float* f_w2 = (const float*)d_in[7];
    const float* f_b2 = (const float*)d_in[8];
    float* out = (float*)d_out;

    cudaFuncSetAttribute(fused_mlp_mma, cudaFuncAttributeMaxDynamicSharedMemorySize, DSMEM_BYTES);
    cudaFuncSetAttribute(fused_mlp_mma, cudaFuncAttributePreferredSharedMemoryCarveout, 100);

    convert_x_kernel<<<1024, 256>>>(x);
    dim3 tg(H_ / 32, D_ / 32);
    transpose_w1_kernel<<<tg, dim3(32, 8)>>>(t_w1, 0);
    transpose_w1_kernel<<<tg, dim3(32, 8)>>>(f_w1, 1);

    dim3 grid(NBLK_N, NBLK_M, 2);   // 64 x 64 x 2, remapped in-kernel
    fused_mlp_mma<<<grid, 256, DSMEM_BYTES>>>(t_b1, t_w2, f_b1, f_w2);

    finalize_kernel<<<(B_ + 255) / 256, 256>>>(t_b2, f_b2, out);
}

// round 11
// speedup vs baseline: 1.0896x; 1.0110x over previous
#include <cuda_runtime.h>
#include <cuda_bf16.h>
#include <cstdint>
#include <math.h>

// ---------------- problem constants ----------------
#define B_ 8192
#define D_ 4096
#define H_ 8192
#define C_ 2

// ---------------- tiling ----------------
#define BM 128
#define BN 128
#define KC 32                    // bf16 K elems per stage (64 bytes per row)
#define NIT (D_ / KC)            // 128
#define NBLK_N (H_ / BN)         // 64
#define NBLK_M (B_ / BM)         // 64
#define NSTAGE 3

// stage layout (bytes): 4 parts of 128 rows x 64B
#define PART_BYTES (128 * 64)            // 8192
#define OFF_AH 0
#define OFF_AL (PART_BYTES)
#define OFF_BH (2 * PART_BYTES)
#define OFF_BL (3 * PART_BYTES)
#define STAGE_BYTES (4 * PART_BYTES)     // 32768
#define DSMEM_BYTES (NSTAGE * STAGE_BYTES)   // 98304

// granule-1 deltas (granule g=tid+256 -> row+64, same chunk)
#define GRAN1_GOFF ((uint64_t)64 * D_ * 2)
#define GRAN1_SOFF 4096

// ---------------- device scratch (no allocs allowed) ----------------
__device__ __nv_bfloat16 g_xhi[(size_t)B_ * D_];
__device__ __nv_bfloat16 g_xlo[(size_t)B_ * D_];
__device__ __nv_bfloat16 g_w1T_hi[2][(size_t)H_ * D_];
__device__ __nv_bfloat16 g_w1T_lo[2][(size_t)H_ * D_];
__device__ float g_part[2][NBLK_N][B_][C_];

// ---------------- helpers ----------------
__device__ __forceinline__ uint32_t smem_u32(const void* p) {
    uint32_t a;
    asm("{ .reg .u64 t; cvta.to.shared.u64 t, %1; cvt.u32.u64 %0, t; }" : "=r"(a) : "l"(p));
    return a;
}
__device__ __forceinline__ uint64_t to_global(const void* p) {
    uint64_t g; asm("cvta.to.global.u64 %0, %1;" : "=l"(g) : "l"(p)); return g;
}
__device__ __forceinline__ void cpa16(uint32_t s, uint64_t g) {
    asm volatile("cp.async.cg.shared.global [%0], [%1], 16;" :: "r"(s), "l"(g));
}
__device__ __forceinline__ void cpa_commit() { asm volatile("cp.async.commit_group;" ::: "memory"); }

__device__ __forceinline__ void ldsm4(uint32_t addr, uint32_t r[4]) {
    asm volatile("ldmatrix.sync.aligned.m8n8.x4.shared.b16 {%0,%1,%2,%3}, [%4];"
        : "=r"(r[0]), "=r"(r[1]), "=r"(r[2]), "=r"(r[3]) : "r"(addr));
}
__device__ __forceinline__ void mma16816(float c[4], const uint32_t a[4], uint32_t b0, uint32_t b1) {
    asm volatile("mma.sync.aligned.m16n8k16.row.col.f32.bf16.bf16.f32 "
        "{%0,%1,%2,%3},{%4,%5,%6,%7},{%8,%9},{%0,%1,%2,%3};"
        : "+f"(c[0]), "+f"(c[1]), "+f"(c[2]), "+f"(c[3])
        : "r"(a[0]), "r"(a[1]), "r"(a[2]), "r"(a[3]), "r"(b0), "r"(b1));
}

// swizzled byte offset for (row, 16B-chunk) inside a 128x64B part
__device__ __forceinline__ uint32_t swz(int row, int ch) {
    return (uint32_t)(row * 64 + ((ch ^ ((row >> 1) & 3)) << 4));
}

// ---------------- conversion kernels ----------------
__global__ void convert_x_kernel(const float* __restrict__ x) {
    size_t i = (size_t)blockIdx.x * blockDim.x + threadIdx.x;
    size_t n = (size_t)B_ * D_;
    size_t stride = (size_t)gridDim.x * blockDim.x;
    for (; i < n; i += stride) {
        float v = x[i];
        __nv_bfloat16 hi = __float2bfloat16_rn(v);
        __nv_bfloat16 lo = __float2bfloat16_rn(v - __bfloat162float(hi));
        g_xhi[i] = hi; g_xlo[i] = lo;
    }
}

__global__ void transpose_w1_kernel(const float* __restrict__ w, int e) {
    __shared__ float t[32][33];
    int tx = threadIdx.x, ty = threadIdx.y;
    int hb = blockIdx.x * 32;   // H origin
    int db = blockIdx.y * 32;   // D origin
    #pragma unroll
    for (int j = 0; j < 4; j++) {
        int d = db + ty + j * 8;
        t[ty + j * 8][tx] = w[(size_t)d * H_ + hb + tx];
    }
    __syncthreads();
    #pragma unroll
    for (int j = 0; j < 4; j++) {
        int h = hb + ty + j * 8;
        float v = t[tx][ty + j * 8];           // w1[db+tx][h]
        __nv_bfloat16 hi = __float2bfloat16_rn(v);
        __nv_bfloat16 lo = __float2bfloat16_rn(v - __bfloat162float(hi));
        size_t o = (size_t)h * D_ + db + tx;
        g_w1T_hi[e][o] = hi; g_w1T_lo[e][o] = lo;
    }
}

// ---------------- fused GEMM1(+bias,ReLU) x w2 ----------------
__global__ __launch_bounds__(256, 2)
void fused_mlp_mma(const float* __restrict__ t_b1, const float* __restrict__ t_w2,
                   const float* __restrict__ f_b1, const float* __restrict__ f_w2)
{
    extern __shared__ char dsm[];
    __shared__ float s_ep[2][BM][2];

    const int tid = threadIdx.x;
    const int lane = tid & 31;
    const int wid = tid >> 5;
    const int warp_m = wid & 3;        // 4 row-bands of 32
    const int warp_n = wid >> 2;       // 2 col-halves of 64

    const uint32_t dbase = smem_u32(dsm);

    // CTA swizzle: groups of 8 m-rows iterate m fastest, then n
    const int e = blockIdx.z;
    const int bid = blockIdx.y * gridDim.x + blockIdx.x;
    const int grp = bid >> 9;               // / (8*64)
    const int r = bid & 511;
    const int mrow = (grp << 3) + (r & 7);
    const int ncol = r >> 3;
    const int m0 = mrow * BM;
    const int n0 = ncol * BN;

    // ---- producer: granule-0 mapping; granule-1 = +GRAN1_GOFF / +GRAN1_SOFF
    const int row0 = tid >> 2, ch0 = tid & 3;
    const uint32_t sA = dbase + swz(row0, ch0);
    const uint64_t go0 = (uint64_t)row0 * (D_ * 2) + (uint64_t)ch0 * 16;

    uint64_t pAh = to_global(g_xhi)       + (uint64_t)m0 * (D_ * 2) + go0;
    uint64_t pAl = to_global(g_xlo)       + (uint64_t)m0 * (D_ * 2) + go0;
    uint64_t pBh = to_global(g_w1T_hi[e]) + (uint64_t)n0 * (D_ * 2) + go0;
    uint64_t pBl = to_global(g_w1T_lo[e]) + (uint64_t)n0 * (D_ * 2) + go0;

    // ---- consumer: 4 rotating base addresses (stage 0), rest by immediates
    const int lr = lane & 15;
    const int lc = lane >> 4;
    uint32_t baseA0 = dbase + OFF_AH + swz(warp_m * 32 + lr, lc);
    uint32_t baseA1 = dbase + OFF_AH + swz(warp_m * 32 + lr, 2 + lc);
    uint32_t baseB0 = dbase + OFF_BH + swz(warp_n * 64 + lr, lc);
    uint32_t baseB1 = dbase + OFF_BH + swz(warp_n * 64 + lr, 2 + lc);

    float acc[2][8][4];
    #pragma unroll
    for (int i = 0; i < 2; i++)
        #pragma unroll
        for (int j = 0; j < 8; j++)
            #pragma unroll
            for (int k = 0; k < 4; k++) acc[i][j][k] = 0.f;

    // ---- producer body (stage chosen by compile-time stoff)
    auto load_stage = [&](uint32_t stoff) {
        cpa16(sA + stoff + OFF_AH,              pAh);
        cpa16(sA + stoff + OFF_AH + GRAN1_SOFF, pAh + GRAN1_GOFF);
        cpa16(sA + stoff + OFF_AL,              pAl);
        cpa16(sA + stoff + OFF_AL + GRAN1_SOFF, pAl + GRAN1_GOFF);
        cpa16(sA + stoff + OFF_BH,              pBh);
        cpa16(sA + stoff + OFF_BH + GRAN1_SOFF, pBh + GRAN1_GOFF);
        cpa16(sA + stoff + OFF_BL,              pBl);
        cpa16(sA + stoff + OFF_BL + GRAN1_SOFF, pBl + GRAN1_GOFF);
        cpa_commit();
        pAh += 64; pAl += 64; pBh += 64; pBl += 64;
    };

    // ---- consume one K chunk; LDSM first, LDGSTS injected after the first
    // 6 LDSM so the MMA-critical loads are ahead in the LSU queue; B frags
    // double-buffered so g+1's LDSM overlaps g's MMAs.
    auto compute = [&](int inject, uint32_t stoff) {
        #pragma unroll
        for (int ks = 0; ks < 2; ks++) {
            const uint32_t bA = ks ? baseA1 : baseA0;
            const uint32_t bB = ks ? baseB1 : baseB0;
            uint32_t aH[2][4], aL[2][4], bH[2][4], bL[2][4];
            ldsm4(bA,                     aH[0]);
            ldsm4(bA + 1024,              aH[1]);
            ldsm4(bA + PART_BYTES,        aL[0]);
            ldsm4(bA + PART_BYTES + 1024, aL[1]);
            ldsm4(bB,                     bH[0]);
            ldsm4(bB + PART_BYTES,        bL[0]);
            if (ks == 0 && inject) load_stage(stoff);
            #pragma unroll
            for (int g = 0; g < 4; g++) {
                const int cur = g & 1, nxt = cur ^ 1;
                if (g < 3) {
                    ldsm4(bB + (g + 1) * 1024,              bH[nxt]);
                    ldsm4(bB + (g + 1) * 1024 + PART_BYTES, bL[nxt]);
                }
                #pragma unroll
                for (int mb = 0; mb < 2; mb++)
                    #pragma unroll
                    for (int o = 0; o < 2; o++) {
                        float* a = acc[mb][g * 2 + o];
                        mma16816(a, aH[mb], bH[cur][o], bH[cur][o + 2]);
                        mma16816(a, aL[mb], bH[cur][o], bH[cur][o + 2]);
                        mma16816(a, aH[mb], bL[cur][o], bL[cur][o + 2]);
                    }
            }
        }
    };

    // prologue: stages 0,1
    load_stage(0);
    load_stage(STAGE_BYTES);

    #define ITER_(PSTOFF, DELTA) do { \
        asm volatile("cp.async.wait_group 1;" ::: "memory"); \
        __syncthreads(); \
        compute(1, (PSTOFF)); \
        baseA0 += (DELTA); baseA1 += (DELTA); \
        baseB0 += (DELTA); baseB1 += (DELTA); \
    } while (0)

    for (int o = 0; o < (NIT - 2) / 3; o++) {
        ITER_(2 * STAGE_BYTES,  STAGE_BYTES);       // consume s0, fill s2
        ITER_(0,                STAGE_BYTES);       // consume s1, fill s0
        ITER_(STAGE_BYTES,     -2 * STAGE_BYTES);   // consume s2, fill s1
    }
    #undef ITER_

    // epilogue iterations 126, 127 (no more loads)
    asm volatile("cp.async.wait_group 1;" ::: "memory");
    __syncthreads();
    compute(0, 0);
    baseA0 += STAGE_BYTES; baseA1 += STAGE_BYTES;
    baseB0 += STAGE_BYTES; baseB1 += STAGE_BYTES;

    asm volatile("cp.async.wait_group 0;" ::: "memory");
    __syncthreads();
    compute(0, 0);

    // ---- epilogue: bias + ReLU + contract with w2 -> per-row partials ----
    const float* __restrict__ b1 = e ? f_b1 : t_b1;
    const float* __restrict__ w2 = e ? f_w2 : t_w2;

    const int qr = lane >> 2;   // acc row within 8
    const int qc = lane & 3;    // acc col pair
    const int n_off = warp_n * 64;

    float s[2][2][2];           // [mblock][rowhalf][class]
    #pragma unroll
    for (int i = 0; i < 2; i++)
        #pragma unroll
        for (int j = 0; j < 2; j++) { s[i][j][0] = 0.f; s[i][j][1] = 0.f; }

    #pragma unroll
    for (int nb = 0; nb < 8; nb++) {
        const int col = n0 + n_off + nb * 8 + qc * 2;
        const float bias0 = __ldg(&b1[col]);
        const float bias1 = __ldg(&b1[col + 1]);
        const float w200 = __ldg(&w2[col * 2 + 0]);
        const float w201 = __ldg(&w2[col * 2 + 1]);
        const float w210 = __ldg(&w2[col * 2 + 2]);
        const float w211 = __ldg(&w2[col * 2 + 3]);
        #pragma unroll
        for (int mb = 0; mb < 2; mb++) {
            float h;
            h = fmaxf(acc[mb][nb][0] + bias0, 0.f); s[mb][0][0] += h * w200; s[mb][0][1] += h * w201;
            h = fmaxf(acc[mb][nb][1] + bias1, 0.f); s[mb][0][0] += h * w210; s[mb][0][1] += h * w211;
            h = fmaxf(acc[mb][nb][2] + bias0, 0.f); s[mb][1][0] += h * w200; s[mb][1][1] += h * w201;
            h = fmaxf(acc[mb][nb][3] + bias1, 0.f); s[mb][1][0] += h * w210; s[mb][1][1] += h * w211;
        }
    }

    // quad butterfly reduce (fixed order -> deterministic)
    #pragma unroll
    for (int mb = 0; mb < 2; mb++)
        #pragma unroll
        for (int rh = 0; rh < 2; rh++)
            #pragma unroll
            for (int c = 0; c < 2; c++) {
                float v = s[mb][rh][c];
                v += __shfl_xor_sync(0xffffffffu, v, 1);
                v += __shfl_xor_sync(0xffffffffu, v, 2);
                s[mb][rh][c] = v;
            }

    if (qc == 0) {
        #pragma unroll
        for (int mb = 0; mb < 2; mb++)
            #pragma unroll
            for (int rh = 0; rh < 2; rh++) {
                const int row = warp_m * 32 + mb * 16 + rh * 8 + qr;
                s_ep[warp_n][row][0] = s[mb][rh][0];
                s_ep[warp_n][row][1] = s[mb][rh][1];
            }
    }
    __syncthreads();

    {
        const int row = tid >> 1, c = tid & 1;
        g_part[e][ncol][m0 + row][c] = s_ep[0][row][c] + s_ep[1][row][c];
    }
}

// ---------------- finalize ----------------
__global__ void finalize_kernel(const float* __restrict__ t_b2,
                                const float* __restrict__ f_b2,
                                float* __restrict__ out)
{
    const int row = blockIdx.x * blockDim.x + threadIdx.x;
    if (row >= B_) return;
    float t0 = t_b2[0], t1 = t_b2[1];
    float f0 = f_b2[0], f1 = f_b2[1];
    #pragma unroll 4
    for (int kb = 0; kb < NBLK_N; kb++) {
        t0 += g_part[0][kb][row][0];
        t1 += g_part[0][kb][row][1];
        f0 += g_part[1][kb][row][0];
        f1 += g_part[1][kb][row][1];
    }
    const float m  = fmaxf(t0, t1);
    const float e0 = __expf(t0 - m);
    const float e1 = __expf(t1 - m);
    const float conf = fmaxf(e0, e1) / (e0 + e1);
    const bool low = conf < 0.8f;
    out[row * 2 + 0] = low ? f0 : t0;
    out[row * 2 + 1] = low ? f1 : t1;
}

// ---------------- launch ----------------
extern "C" void kernel_launch(void* const* d_in, const int* in_sizes, int n_in,
                              void* d_out, int out_size)
{
    const float* x    = (const float*)d_in[0];
    const float* t_w1 = (const float*)d_in[1];
    const float* t_b1 = (const float*)d_in[2];
    const float* t_w2 = (const float*)d_in[3];
    const float* t_b2 = (const float*)d_in[4];
    const float* f_w1 = (const float*)d_in[5];
    const float* f_b1 = (const float*)d_in[6];
    const float* f_w2 = (const float*)d_in[7];
    const float* f_b2 = (const float*)d_in[8];
    float* out = (float*)d_out;

    cudaFuncSetAttribute(fused_mlp_mma, cudaFuncAttributeMaxDynamicSharedMemorySize, DSMEM_BYTES);
    cudaFuncSetAttribute(fused_mlp_mma, cudaFuncAttributePreferredSharedMemoryCarveout, 100);

    convert_x_kernel<<<1024, 256>>>(x);
    dim3 tg(H_ / 32, D_ / 32);
    transpose_w1_kernel<<<tg, dim3(32, 8)>>>(t_w1, 0);
    transpose_w1_kernel<<<tg, dim3(32, 8)>>>(f_w1, 1);

    dim3 grid(NBLK_N, NBLK_M, 2);   // 64 x 64 x 2, remapped in-kernel
    fused_mlp_mma<<<grid, 256, DSMEM_BYTES>>>(t_b1, t_w2, f_b1, f_w2);

    finalize_kernel<<<(B_ + 255) / 256, 256>>>(t_b2, f_b2, out);
}